// round 9
// baseline (speedup 1.0000x reference)
#include <cuda_runtime.h>
#include <cuda_bf16.h>
#include <math_constants.h>

#define NMAX 50000
#define EMAX 1250000
#define FEAT 64
#define NCLS 10
#define NPB  8          // nodes per warp batch in l1trans

#define SCAN_NB 250
#define SCAN_CH 200     // SCAN_NB * SCAN_CH = 50000 >= NMAX

typedef unsigned long long ull;

#define FFMA2(d, a, b) asm("fma.rn.f32x2 %0, %1, %2, %0;" : "+l"(d) : "l"(a), "l"(b))
#define FADD2(d, a)    asm("add.rn.f32x2 %0, %0, %1;"     : "+l"(d) : "l"(a))
#define PACK2(d, x, y) asm("mov.b64 %0, {%1, %2};" : "=l"(d) : "f"(x), "f"(y))
#define UNPK2(x, y, d) asm("mov.b64 {%0, %1}, %2;" : "=f"(x), "=f"(y) : "l"(d))

__device__ int   g_deg[NMAX];
__device__ int   g_off[NMAX + 1];
__device__ int   g_pos[NMAX];
__device__ int   g_srcs[EMAX];
__device__ int   g_scan_state[SCAN_NB];
__device__ int   g_scan_ctr;
__device__ float g_mean[(size_t)NMAX * FEAT];
__device__ float g_y[(size_t)NMAX * 16];   // W2_l @ x1, padded 10->16
__device__ float g_z[(size_t)NMAX * NCLS]; // W2_r @ x1 + b2
__device__ int   g_is64;

// ---------------------------------------------------------------------------
// init (launch #1): dtype detect + scan state reset. Also shifts scatter into
// the profiler's captured slot (#4).
// ---------------------------------------------------------------------------
__global__ void init_kernel(const void* ei, int n) {
    int tid = threadIdx.x;
    if (tid < 32) {
        const long long* p = (const long long*)ei;
        int bad = 0;
        for (int j = tid; j < 64; j += 32) {
            long long v = p[j];
            if (v < 0 || v >= (long long)n) bad = 1;
        }
        bad = __any_sync(0xffffffffu, bad);
        if (tid == 0) { g_is64 = bad ? 0 : 1; g_scan_ctr = 0; }
    }
    if (tid < SCAN_NB) g_scan_state[tid] = 0;
}

// ---------------------------------------------------------------------------
// hist: 2 edges per thread into g_deg (assumed zero on entry).
// ---------------------------------------------------------------------------
__global__ void __launch_bounds__(256) hist_kernel(const void* ei, int E) {
    int is64 = g_is64;
    int e = (blockIdx.x * 256 + threadIdx.x) * 2;
    if (e >= E) return;
    int d0, d1 = -1;
    if (is64) {
        const long long* p = (const long long*)ei + E;
        d0 = (int)p[e];
        if (e + 1 < E) d1 = (int)p[e + 1];
    } else {
        const int* p = (const int*)ei + E;
        d0 = p[e];
        if (e + 1 < E) d1 = p[e + 1];
    }
    atomicAdd(&g_deg[d0], 1);
    if (d1 >= 0) atomicAdd(&g_deg[d1], 1);
}

// ---------------------------------------------------------------------------
// single-pass decoupled-lookback exclusive scan of g_deg -> g_off/g_pos.
// Also zeroes g_deg and writes the g_off[n] = E sentinel.
// ---------------------------------------------------------------------------
__global__ void __launch_bounds__(256) scan_kernel(int n) {
    __shared__ int sh[256];
    __shared__ int sbid;
    __shared__ int sex;
    int t = threadIdx.x;
    if (t == 0) sbid = atomicAdd(&g_scan_ctr, 1);
    __syncthreads();
    int bid = sbid;
    int idx = bid * SCAN_CH + t;
    int v = (t < SCAN_CH && idx < n) ? g_deg[idx] : 0;
    sh[t] = v;
    __syncthreads();
    #pragma unroll
    for (int d = 1; d < 256; d <<= 1) {
        int u = (t >= d) ? sh[t - d] : 0;
        __syncthreads();
        sh[t] += u;
        __syncthreads();
    }
    int total = sh[255];
    if (t == 0) {
        if (bid == 0) {
            atomicExch(&g_scan_state[0], (2 << 30) | total);
            sex = 0;
        } else {
            atomicExch(&g_scan_state[bid], (1 << 30) | total);
            int ex = 0, j = bid - 1;
            while (true) {
                int st = atomicAdd(&g_scan_state[j], 0);
                int f = ((unsigned)st) >> 30;
                if (f == 0) continue;
                ex += st & 0x3FFFFFFF;
                if (f == 2) break;
                --j;
            }
            atomicExch(&g_scan_state[bid], (2 << 30) | (ex + total));
            sex = ex;
        }
    }
    __syncthreads();
    int ex = sex;
    if (t < SCAN_CH && idx < n) {
        int o = ex + sh[t] - v;
        g_off[idx] = o;
        g_pos[idx] = o;
        g_deg[idx] = 0;
    }
    if (bid == SCAN_NB - 1 && t == 0) g_off[n] = ex + total;
}

// ---------------------------------------------------------------------------
// scatter: 2 edges per thread.
// ---------------------------------------------------------------------------
__global__ void __launch_bounds__(256) scatter_kernel(const void* ei, int E) {
    int is64 = g_is64;
    int e = (blockIdx.x * 256 + threadIdx.x) * 2;
    if (e >= E) return;
    int s0, d0, s1 = -1, d1 = -1;
    if (is64) {
        const long long* ps = (const long long*)ei;
        const long long* pd = ps + E;
        s0 = (int)ps[e];  d0 = (int)pd[e];
        if (e + 1 < E) { s1 = (int)ps[e + 1]; d1 = (int)pd[e + 1]; }
    } else {
        const int* ps = (const int*)ei;
        const int* pd = ps + E;
        s0 = ps[e];  d0 = pd[e];
        if (e + 1 < E) { s1 = ps[e + 1]; d1 = pd[e + 1]; }
    }
    int p0 = atomicAdd(&g_pos[d0], 1);
    g_srcs[p0] = s0;
    if (d1 >= 0) {
        int p1 = atomicAdd(&g_pos[d1], 1);
        g_srcs[p1] = s1;
    }
}

// ---------------------------------------------------------------------------
// Layer 1 gather: warp per node, no smem -> high occupancy. Dual packed f32x2
// accumulators. Writes mean row to g_mean. (At the L2 roofline — 320MB.)
// ---------------------------------------------------------------------------
__global__ void __launch_bounds__(256) l1gather_kernel(
    const float* __restrict__ feat, int N)
{
    int tid = threadIdx.x;
    int lane = tid & 31, w = tid >> 5;
    int wg = blockIdx.x * 8 + w;
    int nw = gridDim.x * 8;

    for (int i = wg; i < N; i += nw) {
        int base = g_off[i];
        int deg  = g_off[i + 1] - base;
        ull acc0, acc1;
        PACK2(acc0, 0.f, 0.f);
        PACK2(acc1, 0.f, 0.f);
        for (int j0 = 0; j0 < deg; j0 += 32) {
            int m = deg - j0; if (m > 32) m = 32;
            int s = (lane < m) ? g_srcs[base + j0 + lane] : 0;
            int j = 0;
            #pragma unroll 4
            for (; j + 1 < m; j += 2) {
                int sj0 = __shfl_sync(0xffffffffu, s, j);
                int sj1 = __shfl_sync(0xffffffffu, s, j + 1);
                ull v0 = *(const ull*)(feat + (size_t)sj0 * FEAT + 2 * lane);
                ull v1 = *(const ull*)(feat + (size_t)sj1 * FEAT + 2 * lane);
                FADD2(acc0, v0);
                FADD2(acc1, v1);
            }
            if (j < m) {
                int sj = __shfl_sync(0xffffffffu, s, j);
                ull v = *(const ull*)(feat + (size_t)sj * FEAT + 2 * lane);
                FADD2(acc0, v);
            }
        }
        FADD2(acc0, acc1);
        float ax, ay; UNPK2(ax, ay, acc0);
        float inv = 1.f / fmaxf((float)deg, 1.f);
        *(float2*)(g_mean + (size_t)i * FEAT + 2 * lane) =
            make_float2(ax * inv, ay * inv);
    }
}

// ---------------------------------------------------------------------------
// Fused layer-1 transform + layer-2 transform. NPB=8 nodes per warp per pass.
// Pass A (layer 1): x1 = relu(normalize(Wl@mean + b + Wr@x)), kept in smem.
// Pass B (layer 2): y = W2l@x1 (lanes 0..9), z = W2r@x1 + b2 (lanes 16..25).
// NOTE: no forced min-blocks — smem (72KB) already binds at 3 blocks/SM;
// forcing the reg cap risked spills.
// ---------------------------------------------------------------------------
__global__ void __launch_bounds__(256) l1trans_kernel(
    const float* __restrict__ feat,
    const float* __restrict__ Wl,
    const float* __restrict__ b,
    const float* __restrict__ Wr,
    const float* __restrict__ W2l,
    const float* __restrict__ b2,
    const float* __restrict__ W2r,
    int N)
{
    extern __shared__ char dsm[];
    float4* sWa = (float4*)dsm;                 // 16KB
    float4* sWb = sWa + 32 * 32;                // 16KB
    float2* sW2 = (float2*)(sWb + 32 * 32);     // 8KB
    float2* sV  = sW2 + 32 * 32;                // 32KB: [8 warps][NPB*FEAT]

    int tid = threadIdx.x;
    for (int idx = tid; idx < 32 * 32; idx += 256) {
        int kk = idx >> 5, c = idx & 31;
        int k0 = 2 * kk, k1 = 2 * kk + 1;
        sWa[idx] = make_float4(Wl[c * FEAT + k0],        Wr[c * FEAT + k0],
                               Wl[c * FEAT + k1],        Wr[c * FEAT + k1]);
        sWb[idx] = make_float4(Wl[(c + 32) * FEAT + k0], Wr[(c + 32) * FEAT + k0],
                               Wl[(c + 32) * FEAT + k1], Wr[(c + 32) * FEAT + k1]);
        float2 w2 = make_float2(0.f, 0.f);
        if (c < NCLS)                      w2 = make_float2(W2l[c * FEAT + k0], W2l[c * FEAT + k1]);
        else if (c >= 16 && c < 16 + NCLS) w2 = make_float2(W2r[(c - 16) * FEAT + k0], W2r[(c - 16) * FEAT + k1]);
        sW2[idx] = w2;
    }
    __syncthreads();

    int lane = tid & 31, w = tid >> 5;
    int wg = blockIdx.x * 8 + w;
    int nw = gridDim.x * 8;
    float bias0 = b[lane], bias1 = b[lane + 32];
    float bias2 = (lane >= 16 && lane < 16 + NCLS) ? b2[lane - 16] : 0.f;

    const ulonglong2* sWaq = (const ulonglong2*)sWa;
    const ulonglong2* sWbq = (const ulonglong2*)sWb;
    const ull*        sW2q = (const ull*)sW2;
    float2* sVw = sV + w * (NPB * FEAT);
    const ulonglong2* sVq = (const ulonglong2*)sVw;   // [t*32 + kk]
    float* sXw = (float*)sVw;                          // pass-B reuse: [t*64 + k]

    for (int i0 = wg * NPB; i0 < N; i0 += nw * NPB) {
        // stage NPB nodes of (mean, x) into shared
        #pragma unroll
        for (int t = 0; t < NPB; ++t) {
            int i = i0 + t;
            if (i >= N) break;
            float2 mv = *(const float2*)(g_mean + (size_t)i * FEAT + 2 * lane);
            float2 xv = *(const float2*)(feat   + (size_t)i * FEAT + 2 * lane);
            *(float4*)&sVw[t * FEAT + 2 * lane] = make_float4(mv.x, xv.x, mv.y, xv.y);
        }
        __syncwarp();

        // ---- pass A: layer-1 transform ----
        ull p0[NPB], p1[NPB];
        #pragma unroll
        for (int t = 0; t < NPB; ++t) { PACK2(p0[t], bias0, 0.f); PACK2(p1[t], bias1, 0.f); }
        #pragma unroll
        for (int kk = 0; kk < 32; ++kk) {
            ulonglong2 wa = sWaq[kk * 32 + lane];
            ulonglong2 wb = sWbq[kk * 32 + lane];
            #pragma unroll
            for (int t = 0; t < NPB; ++t) {
                ulonglong2 v = sVq[t * 32 + kk];   // 16B broadcast
                FFMA2(p0[t], wa.x, v.x);
                FFMA2(p0[t], wa.y, v.y);
                FFMA2(p1[t], wb.x, v.x);
                FFMA2(p1[t], wb.y, v.y);
            }
        }
        __syncwarp();   // pass A reads of sV done before overwrite
        #pragma unroll
        for (int t = 0; t < NPB; ++t) {
            int i = i0 + t;
            if (i >= N) break;
            float a, bb, o0, o1;
            UNPK2(a, bb, p0[t]); o0 = a + bb;
            UNPK2(a, bb, p1[t]); o1 = a + bb;
            float ss = o0 * o0 + o1 * o1;
            #pragma unroll
            for (int d = 16; d; d >>= 1) ss += __shfl_xor_sync(0xffffffffu, ss, d);
            float innorm = 1.f / fmaxf(sqrtf(ss), 1e-12f);
            sXw[t * FEAT + lane]      = fmaxf(o0 * innorm, 0.f);
            sXw[t * FEAT + lane + 32] = fmaxf(o1 * innorm, 0.f);
        }
        __syncwarp();

        // ---- pass B: layer-2 transform on x1 rows in smem ----
        ull q[NPB];
        #pragma unroll
        for (int t = 0; t < NPB; ++t) PACK2(q[t], bias2, 0.f);
        #pragma unroll
        for (int kk = 0; kk < 32; ++kk) {
            ull w2 = sW2q[kk * 32 + lane];
            #pragma unroll
            for (int t = 0; t < NPB; ++t) {
                ull v = *(const ull*)&sXw[t * FEAT + 2 * kk];   // broadcast
                FFMA2(q[t], w2, v);
            }
        }
        #pragma unroll
        for (int t = 0; t < NPB; ++t) {
            int i = i0 + t;
            if (i >= N) break;
            float a, bb; UNPK2(a, bb, q[t]);
            float o = a + bb;
            if (lane < NCLS)                   g_y[(size_t)i * 16 + lane] = o;
            else if (lane < 16)                g_y[(size_t)i * 16 + lane] = 0.f;
            else if (lane < 16 + NCLS)         g_z[(size_t)i * NCLS + (lane - 16)] = o;
        }
        __syncwarp();
    }
}

// ---------------------------------------------------------------------------
// Layer 2 gather over 64B g_y rows + epilogue (normalize, log_softmax).
// Lanes 0-15 / 16-31 handle alternating edges; dual accumulators.
// ---------------------------------------------------------------------------
__global__ void __launch_bounds__(256) l2g_kernel(float* __restrict__ out, int N) {
    int tid = threadIdx.x;
    int lane = tid & 31, w = tid >> 5;
    int half = lane >> 4;
    int slot = lane & 15;
    int wg = blockIdx.x * 8 + w;
    int nw = gridDim.x * 8;

    for (int i = wg; i < N; i += nw) {
        int base = g_off[i];
        int deg  = g_off[i + 1] - base;
        float acca = 0.f, accb = 0.f;
        for (int j0 = 0; j0 < deg; j0 += 32) {
            int m = deg - j0; if (m > 32) m = 32;
            int s = (lane < m) ? g_srcs[base + j0 + lane] : 0;
            int np = (m + 1) >> 1;
            int p = 0;
            #pragma unroll 4
            for (; p + 1 < np; p += 2) {
                int ia = 2 * p + half;
                int ib = 2 * (p + 1) + half;
                int sa = __shfl_sync(0xffffffffu, s, ia);
                int sb = __shfl_sync(0xffffffffu, s, ib);
                float va = g_y[(size_t)sa * 16 + slot];
                float vb = g_y[(size_t)sb * 16 + slot];
                if (ia < m) acca += va;
                if (ib < m) accb += vb;
            }
            if (p < np) {
                int ia = 2 * p + half;
                int sa = __shfl_sync(0xffffffffu, s, ia);
                float va = g_y[(size_t)sa * 16 + slot];
                if (ia < m) acca += va;
            }
        }
        float acc = acca + accb;
        acc += __shfl_down_sync(0xffffffffu, acc, 16);
        float inv = 1.f / fmaxf((float)deg, 1.f);
        float o = acc * inv;
        if (lane < NCLS) o += g_z[(size_t)i * NCLS + lane];

        float ss = (lane < NCLS) ? o * o : 0.f;
        #pragma unroll
        for (int d = 16; d; d >>= 1) ss += __shfl_xor_sync(0xffffffffu, ss, d);
        float innorm = 1.f / fmaxf(sqrtf(ss), 1e-12f);
        o *= innorm;
        float mx = (lane < NCLS) ? o : -CUDART_INF_F;
        #pragma unroll
        for (int d = 16; d; d >>= 1) mx = fmaxf(mx, __shfl_xor_sync(0xffffffffu, mx, d));
        float ex = (lane < NCLS) ? expf(o - mx) : 0.f;
        float es = ex;
        #pragma unroll
        for (int d = 16; d; d >>= 1) es += __shfl_xor_sync(0xffffffffu, es, d);
        float lse = logf(es);
        if (lane < NCLS)
            out[(size_t)i * NCLS + lane] = (o - mx) - lse;
    }
}

extern "C" void kernel_launch(void* const* d_in, const int* in_sizes, int n_in,
                              void* d_out, int out_size) {
    const float* feat = (const float*)d_in[0];
    const void*  ei   = d_in[1];
    const float* W1l  = (const float*)d_in[2];
    const float* b1   = (const float*)d_in[3];
    const float* W1r  = (const float*)d_in[4];
    const float* W2l  = (const float*)d_in[5];
    const float* b2   = (const float*)d_in[6];
    const float* W2r  = (const float*)d_in[7];
    float* out = (float*)d_out;

    int N = in_sizes[0] / FEAT;
    int E = in_sizes[1] / 2;
    int Epairs = (E + 1) / 2;

    static int smem_set = 0;
    const int TRANS_SMEM = 72 * 1024;
    if (!smem_set) {
        cudaFuncSetAttribute(l1trans_kernel,
                             cudaFuncAttributeMaxDynamicSharedMemorySize, TRANS_SMEM);
        smem_set = 1;
    }

    init_kernel<<<1, 256>>>(ei, N);                              // 1
    hist_kernel<<<(Epairs + 255) / 256, 256>>>(ei, E);           // 2
    scan_kernel<<<SCAN_NB, 256>>>(N);                            // 3
    scatter_kernel<<<(Epairs + 255) / 256, 256>>>(ei, E);        // 4 <- profiled
    l1gather_kernel<<<1184, 256>>>(feat, N);                     // 5
    l1trans_kernel<<<444, 256, TRANS_SMEM>>>(feat, W1l, b1, W1r,
                                             W2l, b2, W2r, N);   // 6
    l2g_kernel<<<1184, 256>>>(out, N);                           // 7
}

// round 10
// speedup vs baseline: 1.0709x; 1.0709x over previous
#include <cuda_runtime.h>
#include <cuda_bf16.h>
#include <math_constants.h>

#define NMAX 50000
#define EMAX 1250000
#define FEAT 64
#define NCLS 10
#define NPB  8          // nodes per warp batch in l1trans

#define SCAN_NB 250
#define SCAN_CH 200     // SCAN_NB * SCAN_CH = 50000 >= NMAX

typedef unsigned long long ull;

#define FFMA2(d, a, b) asm("fma.rn.f32x2 %0, %1, %2, %0;" : "+l"(d) : "l"(a), "l"(b))
#define FADD2(d, a)    asm("add.rn.f32x2 %0, %0, %1;"     : "+l"(d) : "l"(a))
#define PACK2(d, x, y) asm("mov.b64 %0, {%1, %2};" : "=l"(d) : "f"(x), "f"(y))
#define UNPK2(x, y, d) asm("mov.b64 {%0, %1}, %2;" : "=f"(x), "=f"(y) : "l"(d))

__device__ int   g_deg[NMAX];
__device__ int   g_off[NMAX + 1];
__device__ int   g_rank[EMAX];
__device__ int   g_srcs[EMAX];
__device__ int   g_scan_state[SCAN_NB];
__device__ int   g_scan_ctr;
__device__ float g_mean[(size_t)NMAX * FEAT];
__device__ float g_y[(size_t)NMAX * 16];   // W2_l @ x1, padded 10->16
__device__ float g_z[(size_t)NMAX * NCLS]; // W2_r @ x1 + b2
__device__ int   g_is64;

// ---------------------------------------------------------------------------
// hist: per-block dtype detect, histogram of dst into g_deg (assumed zero),
// per-edge rank capture, and scan-state reset.
// ---------------------------------------------------------------------------
__global__ void __launch_bounds__(256) hist_kernel(const void* ei, int E, int n) {
    __shared__ int sis64;
    int tid = threadIdx.x;
    if (tid < 32) {
        const long long* p = (const long long*)ei;
        int bad = 0;
        for (int j = tid; j < 64; j += 32) {
            long long v = p[j];
            if (v < 0 || v >= (long long)n) bad = 1;
        }
        bad = __any_sync(0xffffffffu, bad);
        if (tid == 0) sis64 = bad ? 0 : 1;
    }
    __syncthreads();
    int is64 = sis64;
    int e = blockIdx.x * 256 + tid;
    if (blockIdx.x == 0 && tid == 0) { g_is64 = is64; g_scan_ctr = 0; }
    if (e < SCAN_NB) g_scan_state[e] = 0;
    if (e >= E) return;
    int d;
    if (is64) d = (int)((const long long*)ei)[E + e];
    else      d = ((const int*)ei)[E + e];
    g_rank[e] = atomicAdd(&g_deg[d], 1);
}

// ---------------------------------------------------------------------------
// single-pass decoupled-lookback exclusive scan of g_deg -> g_off.
// Also zeroes g_deg and writes the g_off[n] = E sentinel.
// ---------------------------------------------------------------------------
__global__ void __launch_bounds__(256) scan_kernel(int n) {
    __shared__ int sh[256];
    __shared__ int sbid;
    __shared__ int sex;
    int t = threadIdx.x;
    if (t == 0) sbid = atomicAdd(&g_scan_ctr, 1);
    __syncthreads();
    int bid = sbid;
    int idx = bid * SCAN_CH + t;
    int v = (t < SCAN_CH && idx < n) ? g_deg[idx] : 0;
    sh[t] = v;
    __syncthreads();
    #pragma unroll
    for (int d = 1; d < 256; d <<= 1) {
        int u = (t >= d) ? sh[t - d] : 0;
        __syncthreads();
        sh[t] += u;
        __syncthreads();
    }
    int total = sh[255];
    if (t == 0) {
        if (bid == 0) {
            atomicExch(&g_scan_state[0], (2 << 30) | total);
            sex = 0;
        } else {
            atomicExch(&g_scan_state[bid], (1 << 30) | total);
            int ex = 0, j = bid - 1;
            while (true) {
                int st = atomicAdd(&g_scan_state[j], 0);
                int f = ((unsigned)st) >> 30;
                if (f == 0) continue;
                ex += st & 0x3FFFFFFF;
                if (f == 2) break;
                --j;
            }
            atomicExch(&g_scan_state[bid], (2 << 30) | (ex + total));
            sex = ex;
        }
    }
    __syncthreads();
    int ex = sex;
    if (t < SCAN_CH && idx < n) {
        g_off[idx] = ex + sh[t] - v;
        g_deg[idx] = 0;
    }
    if (bid == SCAN_NB - 1 && t == 0) g_off[n] = ex + total;
}

// ---------------------------------------------------------------------------
// scatter: atomic-free. pos = off[dst] + rank (rank captured during hist).
// ---------------------------------------------------------------------------
__global__ void __launch_bounds__(256) scatter_kernel(const void* ei, int E) {
    int e = blockIdx.x * blockDim.x + threadIdx.x;
    if (e >= E) return;
    int s, d;
    if (g_is64) {
        const long long* p = (const long long*)ei;
        s = (int)p[e];
        d = (int)p[E + e];
    } else {
        const int* p = (const int*)ei;
        s = p[e];
        d = p[E + e];
    }
    g_srcs[g_off[d] + g_rank[e]] = s;
}

// ---------------------------------------------------------------------------
// Layer 1 gather: warp per node, no smem -> high occupancy. Dual packed f32x2
// accumulators. Writes mean row to g_mean. (At the L2 roofline — 320MB.)
// ---------------------------------------------------------------------------
__global__ void __launch_bounds__(256) l1gather_kernel(
    const float* __restrict__ feat, int N)
{
    int tid = threadIdx.x;
    int lane = tid & 31, w = tid >> 5;
    int wg = blockIdx.x * 8 + w;
    int nw = gridDim.x * 8;

    for (int i = wg; i < N; i += nw) {
        int base = g_off[i];
        int deg  = g_off[i + 1] - base;
        ull acc0, acc1;
        PACK2(acc0, 0.f, 0.f);
        PACK2(acc1, 0.f, 0.f);
        for (int j0 = 0; j0 < deg; j0 += 32) {
            int m = deg - j0; if (m > 32) m = 32;
            int s = (lane < m) ? g_srcs[base + j0 + lane] : 0;
            int j = 0;
            #pragma unroll 4
            for (; j + 1 < m; j += 2) {
                int sj0 = __shfl_sync(0xffffffffu, s, j);
                int sj1 = __shfl_sync(0xffffffffu, s, j + 1);
                ull v0 = *(const ull*)(feat + (size_t)sj0 * FEAT + 2 * lane);
                ull v1 = *(const ull*)(feat + (size_t)sj1 * FEAT + 2 * lane);
                FADD2(acc0, v0);
                FADD2(acc1, v1);
            }
            if (j < m) {
                int sj = __shfl_sync(0xffffffffu, s, j);
                ull v = *(const ull*)(feat + (size_t)sj * FEAT + 2 * lane);
                FADD2(acc0, v);
            }
        }
        FADD2(acc0, acc1);
        float ax, ay; UNPK2(ax, ay, acc0);
        float inv = 1.f / fmaxf((float)deg, 1.f);
        *(float2*)(g_mean + (size_t)i * FEAT + 2 * lane) =
            make_float2(ax * inv, ay * inv);
    }
}

// ---------------------------------------------------------------------------
// Fused layer-1 transform + layer-2 transform. NPB=8 nodes per warp per pass.
// Pass A (layer 1): x1 = relu(normalize(Wl@mean + b + Wr@x)), kept in smem.
// Pass B (layer 2): y = W2l@x1 (lanes 0..9), z = W2r@x1 + b2 (lanes 16..25).
// __launch_bounds__(256,3): smem binds at 3 blocks/SM; cap regs to 84 so the
// register file admits 3 blocks too (R8-proven).
// ---------------------------------------------------------------------------
__global__ void __launch_bounds__(256, 3) l1trans_kernel(
    const float* __restrict__ feat,
    const float* __restrict__ Wl,
    const float* __restrict__ b,
    const float* __restrict__ Wr,
    const float* __restrict__ W2l,
    const float* __restrict__ b2,
    const float* __restrict__ W2r,
    int N)
{
    extern __shared__ char dsm[];
    float4* sWa = (float4*)dsm;                 // 16KB
    float4* sWb = sWa + 32 * 32;                // 16KB
    float2* sW2 = (float2*)(sWb + 32 * 32);     // 8KB
    float2* sV  = sW2 + 32 * 32;                // 32KB: [8 warps][NPB*FEAT]

    int tid = threadIdx.x;
    for (int idx = tid; idx < 32 * 32; idx += 256) {
        int kk = idx >> 5, c = idx & 31;
        int k0 = 2 * kk, k1 = 2 * kk + 1;
        sWa[idx] = make_float4(Wl[c * FEAT + k0],        Wr[c * FEAT + k0],
                               Wl[c * FEAT + k1],        Wr[c * FEAT + k1]);
        sWb[idx] = make_float4(Wl[(c + 32) * FEAT + k0], Wr[(c + 32) * FEAT + k0],
                               Wl[(c + 32) * FEAT + k1], Wr[(c + 32) * FEAT + k1]);
        float2 w2 = make_float2(0.f, 0.f);
        if (c < NCLS)                      w2 = make_float2(W2l[c * FEAT + k0], W2l[c * FEAT + k1]);
        else if (c >= 16 && c < 16 + NCLS) w2 = make_float2(W2r[(c - 16) * FEAT + k0], W2r[(c - 16) * FEAT + k1]);
        sW2[idx] = w2;
    }
    __syncthreads();

    int lane = tid & 31, w = tid >> 5;
    int wg = blockIdx.x * 8 + w;
    int nw = gridDim.x * 8;
    float bias0 = b[lane], bias1 = b[lane + 32];
    float bias2 = (lane >= 16 && lane < 16 + NCLS) ? b2[lane - 16] : 0.f;

    const ulonglong2* sWaq = (const ulonglong2*)sWa;
    const ulonglong2* sWbq = (const ulonglong2*)sWb;
    const ull*        sW2q = (const ull*)sW2;
    float2* sVw = sV + w * (NPB * FEAT);
    const ulonglong2* sVq = (const ulonglong2*)sVw;   // [t*32 + kk]
    float* sXw = (float*)sVw;                          // pass-B reuse: [t*64 + k]

    for (int i0 = wg * NPB; i0 < N; i0 += nw * NPB) {
        // stage NPB nodes of (mean, x) into shared
        #pragma unroll
        for (int t = 0; t < NPB; ++t) {
            int i = i0 + t;
            if (i >= N) break;
            float2 mv = *(const float2*)(g_mean + (size_t)i * FEAT + 2 * lane);
            float2 xv = *(const float2*)(feat   + (size_t)i * FEAT + 2 * lane);
            *(float4*)&sVw[t * FEAT + 2 * lane] = make_float4(mv.x, xv.x, mv.y, xv.y);
        }
        __syncwarp();

        // ---- pass A: layer-1 transform ----
        ull p0[NPB], p1[NPB];
        #pragma unroll
        for (int t = 0; t < NPB; ++t) { PACK2(p0[t], bias0, 0.f); PACK2(p1[t], bias1, 0.f); }
        #pragma unroll
        for (int kk = 0; kk < 32; ++kk) {
            ulonglong2 wa = sWaq[kk * 32 + lane];
            ulonglong2 wb = sWbq[kk * 32 + lane];
            #pragma unroll
            for (int t = 0; t < NPB; ++t) {
                ulonglong2 v = sVq[t * 32 + kk];   // 16B broadcast
                FFMA2(p0[t], wa.x, v.x);
                FFMA2(p0[t], wa.y, v.y);
                FFMA2(p1[t], wb.x, v.x);
                FFMA2(p1[t], wb.y, v.y);
            }
        }
        __syncwarp();   // pass A reads of sV done before overwrite
        #pragma unroll
        for (int t = 0; t < NPB; ++t) {
            int i = i0 + t;
            if (i >= N) break;
            float a, bb, o0, o1;
            UNPK2(a, bb, p0[t]); o0 = a + bb;
            UNPK2(a, bb, p1[t]); o1 = a + bb;
            float ss = o0 * o0 + o1 * o1;
            #pragma unroll
            for (int d = 16; d; d >>= 1) ss += __shfl_xor_sync(0xffffffffu, ss, d);
            float innorm = 1.f / fmaxf(sqrtf(ss), 1e-12f);
            sXw[t * FEAT + lane]      = fmaxf(o0 * innorm, 0.f);
            sXw[t * FEAT + lane + 32] = fmaxf(o1 * innorm, 0.f);
        }
        __syncwarp();

        // ---- pass B: layer-2 transform on x1 rows in smem ----
        ull q[NPB];
        #pragma unroll
        for (int t = 0; t < NPB; ++t) PACK2(q[t], bias2, 0.f);
        #pragma unroll
        for (int kk = 0; kk < 32; ++kk) {
            ull w2 = sW2q[kk * 32 + lane];
            #pragma unroll
            for (int t = 0; t < NPB; ++t) {
                ull v = *(const ull*)&sXw[t * FEAT + 2 * kk];   // broadcast
                FFMA2(q[t], w2, v);
            }
        }
        #pragma unroll
        for (int t = 0; t < NPB; ++t) {
            int i = i0 + t;
            if (i >= N) break;
            float a, bb; UNPK2(a, bb, q[t]);
            float o = a + bb;
            if (lane < NCLS)                   g_y[(size_t)i * 16 + lane] = o;
            else if (lane < 16)                g_y[(size_t)i * 16 + lane] = 0.f;
            else if (lane < 16 + NCLS)         g_z[(size_t)i * NCLS + (lane - 16)] = o;
        }
        __syncwarp();
    }
}

// ---------------------------------------------------------------------------
// Layer 2 gather over 64B g_y rows + epilogue (normalize, log_softmax).
// Lanes 0-15 / 16-31 handle alternating edges; dual accumulators.
// ---------------------------------------------------------------------------
__global__ void __launch_bounds__(256) l2g_kernel(float* __restrict__ out, int N) {
    int tid = threadIdx.x;
    int lane = tid & 31, w = tid >> 5;
    int half = lane >> 4;
    int slot = lane & 15;
    int wg = blockIdx.x * 8 + w;
    int nw = gridDim.x * 8;

    for (int i = wg; i < N; i += nw) {
        int base = g_off[i];
        int deg  = g_off[i + 1] - base;
        float acca = 0.f, accb = 0.f;
        for (int j0 = 0; j0 < deg; j0 += 32) {
            int m = deg - j0; if (m > 32) m = 32;
            int s = (lane < m) ? g_srcs[base + j0 + lane] : 0;
            int np = (m + 1) >> 1;
            int p = 0;
            #pragma unroll 4
            for (; p + 1 < np; p += 2) {
                int ia = 2 * p + half;
                int ib = 2 * (p + 1) + half;
                int sa = __shfl_sync(0xffffffffu, s, ia);
                int sb = __shfl_sync(0xffffffffu, s, ib);
                float va = g_y[(size_t)sa * 16 + slot];
                float vb = g_y[(size_t)sb * 16 + slot];
                if (ia < m) acca += va;
                if (ib < m) accb += vb;
            }
            if (p < np) {
                int ia = 2 * p + half;
                int sa = __shfl_sync(0xffffffffu, s, ia);
                float va = g_y[(size_t)sa * 16 + slot];
                if (ia < m) acca += va;
            }
        }
        float acc = acca + accb;
        acc += __shfl_down_sync(0xffffffffu, acc, 16);
        float inv = 1.f / fmaxf((float)deg, 1.f);
        float o = acc * inv;
        if (lane < NCLS) o += g_z[(size_t)i * NCLS + lane];

        float ss = (lane < NCLS) ? o * o : 0.f;
        #pragma unroll
        for (int d = 16; d; d >>= 1) ss += __shfl_xor_sync(0xffffffffu, ss, d);
        float innorm = 1.f / fmaxf(sqrtf(ss), 1e-12f);
        o *= innorm;
        float mx = (lane < NCLS) ? o : -CUDART_INF_F;
        #pragma unroll
        for (int d = 16; d; d >>= 1) mx = fmaxf(mx, __shfl_xor_sync(0xffffffffu, mx, d));
        float ex = (lane < NCLS) ? expf(o - mx) : 0.f;
        float es = ex;
        #pragma unroll
        for (int d = 16; d; d >>= 1) es += __shfl_xor_sync(0xffffffffu, es, d);
        float lse = logf(es);
        if (lane < NCLS)
            out[(size_t)i * NCLS + lane] = (o - mx) - lse;
    }
}

extern "C" void kernel_launch(void* const* d_in, const int* in_sizes, int n_in,
                              void* d_out, int out_size) {
    const float* feat = (const float*)d_in[0];
    const void*  ei   = d_in[1];
    const float* W1l  = (const float*)d_in[2];
    const float* b1   = (const float*)d_in[3];
    const float* W1r  = (const float*)d_in[4];
    const float* W2l  = (const float*)d_in[5];
    const float* b2   = (const float*)d_in[6];
    const float* W2r  = (const float*)d_in[7];
    float* out = (float*)d_out;

    int N = in_sizes[0] / FEAT;
    int E = in_sizes[1] / 2;

    static int smem_set = 0;
    const int TRANS_SMEM = 72 * 1024;
    if (!smem_set) {
        cudaFuncSetAttribute(l1trans_kernel,
                             cudaFuncAttributeMaxDynamicSharedMemorySize, TRANS_SMEM);
        smem_set = 1;
    }

    hist_kernel<<<(E + 255) / 256, 256>>>(ei, E, N);             // 1
    scan_kernel<<<SCAN_NB, 256>>>(N);                            // 2
    scatter_kernel<<<(E + 255) / 256, 256>>>(ei, E);             // 3
    l1gather_kernel<<<1184, 256>>>(feat, N);                     // 4 <- profiled
    l1trans_kernel<<<444, 256, TRANS_SMEM>>>(feat, W1l, b1, W1r,
                                             W2l, b2, W2r, N);   // 5
    l2g_kernel<<<1184, 256>>>(out, N);                           // 6
}